// round 7
// baseline (speedup 1.0000x reference)
#include <cuda_runtime.h>

#define BB 256
#define SS 4096
#define HH 64
#define NG 256   // 4*H gates

// Scratch (allocation-free: static device globals)
__device__ float g_buf0[(size_t)BB * SS * HH];
__device__ float g_buf1[(size_t)BB * SS * HH];
__device__ float g_xg[(size_t)BB * SS * NG];   // gate-interleaved: [b,s,hh*4+q]

typedef unsigned long long ull;

// ---- packed f32x2 helpers (FFMA2 path, sm_103a) ----
__device__ __forceinline__ ull pk2(float lo, float hi) {
    ull r; asm("mov.b64 %0,{%1,%2};" : "=l"(r) : "f"(lo), "f"(hi)); return r;
}
__device__ __forceinline__ void upk2(ull v, float& lo, float& hi) {
    asm("mov.b64 {%0,%1},%2;" : "=f"(lo), "=f"(hi) : "l"(v));
}
__device__ __forceinline__ ull ffma2(ull a, ull b, ull c) {
    ull d; asm("fma.rn.f32x2 %0,%1,%2,%3;" : "=l"(d) : "l"(a), "l"(b), "l"(c)); return d;
}

// sigmoid via MUFU (err ~1e-6). tanh(x) = 2*sig(2x)-1 (exact identity).
__device__ __forceinline__ float sig_(float x) {
    float e = __expf(-x);
    return __fdividef(1.f, 1.f + e);
}
__device__ __forceinline__ float tanh_(float x) {
    return 2.f * sig_(2.f * x) - 1.f;
}

// ============================================================================
// xgemm: xg[b,s, hh*4+q] = (bih+bhh)[q*64+hh] + Wih[q*64+hh,:] . hs[b,s,:]
// Grid 256 = (128 batch pairs) x (2 s-halves); 256 threads. Unchanged (R5).
// ============================================================================
__global__ __launch_bounds__(256, 1)
void xgemm(const float* __restrict__ hs, const float* __restrict__ Wih,
           const float* __restrict__ bih, const float* __restrict__ bhh,
           float* __restrict__ xg) {
    const int gq = threadIdx.x;
    const int q = gq & 3, hh = gq >> 2;
    const int row = q * HH + hh;
    const int b0 = (blockIdx.x >> 1) * 2;
    const int s0 = (blockIdx.x & 1) * (SS / 2);

    __shared__ float4 sh[2][16][16];   // [parity][chunk row][16 float4]

    ull w[32];
    {
        const float4* Wr = reinterpret_cast<const float4*>(Wih + row * HH);
#pragma unroll
        for (int k = 0; k < 16; k++) {
            float4 v = Wr[k];
            w[2 * k] = pk2(v.x, v.y);
            w[2 * k + 1] = pk2(v.z, v.w);
        }
    }
    const float bias = bih[row] + bhh[row];

    const int bb = gq >> 7, so = (gq >> 4) & 7, qq = gq & 15;
    const size_t ldb = ((size_t)(b0 + bb) * SS + s0 + so) * 16 + qq;  // float4 units
    const float4* hs4 = reinterpret_cast<const float4*>(hs);

    sh[0][bb * 8 + so][qq] = hs4[ldb];   // prime chunk 0

    int p = 0;
    const int NCH = (SS / 2) / 8;  // 256 chunks
    for (int ch = 0; ch < NCH; ++ch) {
        __syncthreads();
        float4 nxt;
        if (ch + 1 < NCH) nxt = hs4[ldb + (size_t)(ch + 1) * 128];

#pragma unroll
        for (int rp = 0; rp < 8; ++rp) {
            const int r0 = 2 * rp, r1 = r0 + 1;
            ull a0 = pk2(bias, 0.f);
            ull a1 = pk2(bias, 0.f);
            const ulonglong2* v0 = reinterpret_cast<const ulonglong2*>(sh[p][r0]);
            const ulonglong2* v1 = reinterpret_cast<const ulonglong2*>(sh[p][r1]);
#pragma unroll
            for (int k = 0; k < 16; k++) {
                ulonglong2 p0 = v0[k];
                ulonglong2 p1 = v1[k];
                a0 = ffma2(w[2 * k], p0.x, a0);
                a0 = ffma2(w[2 * k + 1], p0.y, a0);
                a1 = ffma2(w[2 * k], p1.x, a1);
                a1 = ffma2(w[2 * k + 1], p1.y, a1);
            }
            float l, h;
            upk2(a0, l, h); float sA = l + h;
            upk2(a1, l, h); float sB = l + h;
            xg[((size_t)(b0 + (r0 >> 3)) * SS + s0 + (size_t)ch * 8 + (r0 & 7)) * NG + gq] = sA;
            xg[((size_t)(b0 + (r1 >> 3)) * SS + s0 + (size_t)ch * 8 + (r1 & 7)) * NG + gq] = sB;
        }
        if (ch + 1 < NCH) sh[p ^ 1][bb * 8 + so][qq] = nxt;
        p ^= 1;
    }
}

// ============================================================================
// LSTM scan: 128 CTAs x 512 threads, 2 batches/CTA (R5 skeleton), but
// 1 gate-row per thread -> 4 warps per SMSP to hide the serial chain.
// Thread j: bl=j>>8 (batch), hh=(j>>2)&63, q=j&3 (gate i/f/g/o), row=q*64+hh.
// Whh row in regs (32 ull = 64 regs; ~115 total, fits 512thr occ-1).
// Gate exchange: 3 bfly shfls in the lane quad. ONE barrier/step.
// ============================================================================
template <bool L0>
__global__ __launch_bounds__(512, 1)
void lstm_scan(const float* __restrict__ xin,   // L0: x [B,S,1]; else xg [B,S,256]
               const float* __restrict__ Wih,   // L0 only: [256,1]
               const float* __restrict__ Whh,
               const float* __restrict__ bih, const float* __restrict__ bhh,
               float* __restrict__ hsout,
               float* __restrict__ hn, float* __restrict__ cn) {
    const int j = threadIdx.x;
    const int bl = j >> 8;           // local batch 0/1
    const int r = j & 255;           // row slot hh*4+q
    const int q = r & 3;
    const int hh = r >> 2;
    const int row = q * HH + hh;
    const int b = blockIdx.x * 2 + bl;

    __shared__ float4 sh_h[2][2][16];   // [parity][bl][64 floats]

    ull w[32];
    {
        const float4* Wr = reinterpret_cast<const float4*>(Whh + row * HH);
#pragma unroll
        for (int k = 0; k < 16; k++) {
            float4 v = Wr[k];
            w[2 * k] = pk2(v.x, v.y);
            w[2 * k + 1] = pk2(v.z, v.w);
        }
    }
    float w0 = 0.f, bias = 0.f;
    if (L0) { w0 = Wih[row]; bias = bih[row] + bhh[row]; }

    // activation params: A = m*sig(m*g) - d  (g-gate -> tanh)
    const float m0 = (q == 2) ? 2.f : 1.f;
    const float d0 = (q == 2) ? 1.f : 0.f;

    // zero h parity 0, both batches
    if (j < 32) sh_h[0][j >> 4][j & 15] = make_float4(0.f, 0.f, 0.f, 0.f);

    // ---- x stream, depth-2 register prefetch ----
    float xc, xn;
    size_t xb;
    if (L0) {
        xb = (size_t)b * SS;            // uniform scalar per step
        xc = xin[xb];
        xn = xin[xb + 1];
    } else {
        xb = (size_t)b * SS * NG + r;   // coalesced float per thread per step
        xc = xin[xb];
        xn = xin[xb + (size_t)NG];
    }
    __syncthreads();

    float c = 0.f;

    for (int t = 0; t < SS; ++t) {
        const int pr = t & 1;

        // prefetch t+2 early (covers DRAM/L2 latency across the step)
        float pf = 0.f;
        if (t + 2 < SS) pf = xin[xb + (L0 ? (size_t)(t + 2) : (size_t)(t + 2) * NG)];

        // ax for this step
        const float ax = L0 ? fmaf(w0, xc, bias) : xc;

        // g = ax + Whh . h_{t-1}  (two 8-deep chains)
        ull a0 = pk2(ax, 0.f);
        ull a1 = pk2(0.f, 0.f);
        const ulonglong2* vh = reinterpret_cast<const ulonglong2*>(sh_h[pr][bl]);
#pragma unroll
        for (int k = 0; k < 8; k++) {
            ulonglong2 p0 = vh[k];
            ulonglong2 p1 = vh[8 + k];
            a0 = ffma2(w[2 * k], p0.x, a0);
            a0 = ffma2(w[2 * k + 1], p0.y, a0);
            a1 = ffma2(w[16 + 2 * k], p1.x, a1);
            a1 = ffma2(w[17 + 2 * k], p1.y, a1);
        }
        float l, h;
        upk2(a0, l, h); float s = l + h;
        upk2(a1, l, h); s += l + h;

        // activation (branchless per-thread constants)
        float A = m0 * sig_(m0 * s) - d0;

        // quad butterfly: gather all 4 gates of unit hh (intra-warp)
        float Ax = __shfl_xor_sync(0xffffffffu, A, 1);    // gate q^1
        float By = __shfl_xor_sync(0xffffffffu, A, 2);    // gate q^2
        float Bz = __shfl_xor_sync(0xffffffffu, Ax, 2);   // gate q^3
        float iv = (q == 0) ? A : (q == 1) ? Ax : (q == 2) ? By : Bz;
        float fv = (q == 1) ? A : (q == 0) ? Ax : (q == 3) ? By : Bz;
        float gv = (q == 2) ? A : (q == 3) ? Ax : (q == 0) ? By : Bz;
        float ov = (q == 3) ? A : (q == 2) ? Ax : (q == 1) ? By : Bz;

        // identical update in all 4 quad lanes (deterministic)
        c = fv * c + iv * gv;
        float hv = ov * tanh_(c);

        if (q == 0) {
            reinterpret_cast<float*>(sh_h[pr ^ 1][bl])[hh] = hv;
        } else if (q == 1) {
            hsout[((size_t)b * SS + t) * HH + hh] = hv;
            if (t == SS - 1) hn[b * HH + hh] = hv;
        } else if (q == 2) {
            if (t == SS - 1) cn[b * HH + hh] = c;
        }
        __syncthreads();   // h_t visible for step t+1

        xc = xn;
        xn = pf;
    }
}

// Final projection: thread-per-output, 16 consecutive LDG.128 per thread.
__global__ __launch_bounds__(256)
void proj_kernel(const float* __restrict__ hs, const float* __restrict__ Wlin,
                 const float* __restrict__ blin, float* __restrict__ y) {
    __shared__ float4 w[16];
    __shared__ float bsh;
    if (threadIdx.x < 16) w[threadIdx.x] = reinterpret_cast<const float4*>(Wlin)[threadIdx.x];
    if (threadIdx.x == 16) bsh = blin[0];
    __syncthreads();
    size_t o = (size_t)blockIdx.x * 256 + threadIdx.x;
    const float4* v = reinterpret_cast<const float4*>(hs + o * HH);
    float acc = 0.f;
#pragma unroll
    for (int k = 0; k < 16; k++) {
        float4 a = v[k];
        float4 b = w[k];
        acc += a.x * b.x + a.y * b.y + a.z * b.z + a.w * b.w;
    }
    y[o] = acc + bsh;
}

extern "C" void kernel_launch(void* const* d_in, const int* in_sizes, int n_in,
                              void* d_out, int out_size) {
    const float* x    = (const float*)d_in[0];
    const float* Wih0 = (const float*)d_in[1];
    const float* Whh0 = (const float*)d_in[2];
    const float* bih0 = (const float*)d_in[3];
    const float* bhh0 = (const float*)d_in[4];
    const float* Wih1 = (const float*)d_in[5];
    const float* Whh1 = (const float*)d_in[6];
    const float* bih1 = (const float*)d_in[7];
    const float* bhh1 = (const float*)d_in[8];
    const float* Wih2 = (const float*)d_in[9];
    const float* Whh2 = (const float*)d_in[10];
    const float* bih2 = (const float*)d_in[11];
    const float* bhh2 = (const float*)d_in[12];
    const float* Wlin = (const float*)d_in[13];
    const float* blin = (const float*)d_in[14];

    float* y  = (float*)d_out;                 // [B,S,1]
    float* hn = y + (size_t)BB * SS;           // [3,B,H]
    float* cn = hn + (size_t)3 * BB * HH;      // [3,B,H]

    float *buf0, *buf1, *xg;
    cudaGetSymbolAddress((void**)&buf0, g_buf0);
    cudaGetSymbolAddress((void**)&buf1, g_buf1);
    cudaGetSymbolAddress((void**)&xg,  g_xg);

    // Layer 0: inline scalar x (DIN=1)
    lstm_scan<true ><<<BB / 2, 512>>>(x, Wih0, Whh0, bih0, bhh0, buf0, hn, cn);
    // Layer 1: precompute interleaved xg, then h-only scan
    xgemm<<<BB, 256>>>(buf0, Wih1, bih1, bhh1, xg);
    lstm_scan<false><<<BB / 2, 512>>>(xg, Wih1, Whh1, bih1, bhh1, buf1,
                                      hn + BB * HH, cn + BB * HH);
    // Layer 2
    xgemm<<<BB, 256>>>(buf1, Wih2, bih2, bhh2, xg);
    lstm_scan<false><<<BB / 2, 512>>>(xg, Wih2, Whh2, bih2, bhh2, buf0,
                                      hn + 2 * BB * HH, cn + 2 * BB * HH);

    proj_kernel<<<(BB * SS) / 256, 256>>>(buf0, Wlin, blin, y);
}

// round 8
// speedup vs baseline: 1.3242x; 1.3242x over previous
#include <cuda_runtime.h>

#define BB 256
#define SS 4096
#define HH 64
#define NG 256   // 4*H gates

// Scratch (allocation-free: static device globals)
__device__ float g_buf0[(size_t)BB * SS * HH];
__device__ float g_buf1[(size_t)BB * SS * HH];
__device__ float g_xg[(size_t)BB * SS * NG];   // gate-interleaved: [b,s,hh*4+q]

typedef unsigned long long ull;

// ---- packed f32x2 helpers (FFMA2 path, sm_103a) ----
__device__ __forceinline__ ull pk2(float lo, float hi) {
    ull r; asm("mov.b64 %0,{%1,%2};" : "=l"(r) : "f"(lo), "f"(hi)); return r;
}
__device__ __forceinline__ void upk2(ull v, float& lo, float& hi) {
    asm("mov.b64 {%0,%1},%2;" : "=f"(lo), "=f"(hi) : "l"(v));
}
__device__ __forceinline__ ull ffma2(ull a, ull b, ull c) {
    ull d; asm("fma.rn.f32x2 %0,%1,%2,%3;" : "=l"(d) : "l"(a), "l"(b), "l"(c)); return d;
}

// sigmoid via MUFU (err ~1e-6). tanh(x) = 2*sig(2x)-1 (exact identity).
__device__ __forceinline__ float sig_(float x) {
    float e = __expf(-x);
    return __fdividef(1.f, 1.f + e);
}
__device__ __forceinline__ float tanh_(float x) {
    return 2.f * sig_(2.f * x) - 1.f;
}

// Named barrier over one batch's 128 threads (4 warps). ids 1,2.
#define BATCH_BAR(bl) asm volatile("bar.sync %0, 128;" :: "r"((bl) + 1) : "memory")

// ============================================================================
// xgemm: xg[b,s, hh*4+q] = (bih+bhh)[q*64+hh] + Wih[q*64+hh,:] . hs[b,s,:]
// Unchanged from R5 (best known).
// ============================================================================
__global__ __launch_bounds__(256, 1)
void xgemm(const float* __restrict__ hs, const float* __restrict__ Wih,
           const float* __restrict__ bih, const float* __restrict__ bhh,
           float* __restrict__ xg) {
    const int gq = threadIdx.x;
    const int q = gq & 3, hh = gq >> 2;
    const int row = q * HH + hh;
    const int b0 = (blockIdx.x >> 1) * 2;
    const int s0 = (blockIdx.x & 1) * (SS / 2);

    __shared__ float4 sh[2][16][16];   // [parity][chunk row][16 float4]

    ull w[32];
    {
        const float4* Wr = reinterpret_cast<const float4*>(Wih + row * HH);
#pragma unroll
        for (int k = 0; k < 16; k++) {
            float4 v = Wr[k];
            w[2 * k] = pk2(v.x, v.y);
            w[2 * k + 1] = pk2(v.z, v.w);
        }
    }
    const float bias = bih[row] + bhh[row];

    const int bb = gq >> 7, so = (gq >> 4) & 7, qq = gq & 15;
    const size_t ldb = ((size_t)(b0 + bb) * SS + s0 + so) * 16 + qq;  // float4 units
    const float4* hs4 = reinterpret_cast<const float4*>(hs);

    sh[0][bb * 8 + so][qq] = hs4[ldb];   // prime chunk 0

    int p = 0;
    const int NCH = (SS / 2) / 8;  // 256 chunks
    for (int ch = 0; ch < NCH; ++ch) {
        __syncthreads();
        float4 nxt;
        if (ch + 1 < NCH) nxt = hs4[ldb + (size_t)(ch + 1) * 128];

#pragma unroll
        for (int rp = 0; rp < 8; ++rp) {
            const int r0 = 2 * rp, r1 = r0 + 1;
            ull a0 = pk2(bias, 0.f);
            ull a1 = pk2(bias, 0.f);
            const ulonglong2* v0 = reinterpret_cast<const ulonglong2*>(sh[p][r0]);
            const ulonglong2* v1 = reinterpret_cast<const ulonglong2*>(sh[p][r1]);
#pragma unroll
            for (int k = 0; k < 16; k++) {
                ulonglong2 p0 = v0[k];
                ulonglong2 p1 = v1[k];
                a0 = ffma2(w[2 * k], p0.x, a0);
                a0 = ffma2(w[2 * k + 1], p0.y, a0);
                a1 = ffma2(w[2 * k], p1.x, a1);
                a1 = ffma2(w[2 * k + 1], p1.y, a1);
            }
            float l, h;
            upk2(a0, l, h); float sA = l + h;
            upk2(a1, l, h); float sB = l + h;
            xg[((size_t)(b0 + (r0 >> 3)) * SS + s0 + (size_t)ch * 8 + (r0 & 7)) * NG + gq] = sA;
            xg[((size_t)(b0 + (r1 >> 3)) * SS + s0 + (size_t)ch * 8 + (r1 & 7)) * NG + gq] = sB;
        }
        if (ch + 1 < NCH) sh[p ^ 1][bb * 8 + so][qq] = nxt;
        p ^= 1;
    }
}

// ============================================================================
// LSTM scan = R5 winner (256 thr, 2 batches/CTA, 2 rows/thread, pair-shfl,
// one barrier/step) + micro-opts:
//   * per-batch named barriers (bar.sync 1+b, 128) — decouple the two batches
//   * explicit h preload bursts (MLP 8) before the FMA chains
//   * pointer-walk for the x/xg stream
// ============================================================================
template <bool L0>
__global__ __launch_bounds__(256, 1)
void lstm_scan(const float* __restrict__ xin,   // L0: x [B,S,1]; else xg [B,S,256]
               const float* __restrict__ Wih,   // L0 only: [256,1]
               const float* __restrict__ Whh,
               const float* __restrict__ bih, const float* __restrict__ bhh,
               float* __restrict__ hsout,
               float* __restrict__ hn, float* __restrict__ cn) {
    const int j = threadIdx.x;
    const int p = j & 1;
    const int hh = (j >> 1) & 63;
    const int b = j >> 7;
    const int b0 = blockIdx.x * 2;
    const int row0 = p * 128 + hh;        // p0: i-row ; p1: g-row
    const int row1 = p * 128 + 64 + hh;   // p0: f-row ; p1: o-row

    __shared__ float4 sh_h[2][2][16];   // [parity][b][64 floats]

    ull wA[32], wB[32];
    {
        const float4* Wr = reinterpret_cast<const float4*>(Whh + row0 * HH);
#pragma unroll
        for (int k = 0; k < 16; k++) {
            float4 v = Wr[k];
            wA[2 * k] = pk2(v.x, v.y);
            wA[2 * k + 1] = pk2(v.z, v.w);
        }
        const float4* Wr2 = reinterpret_cast<const float4*>(Whh + row1 * HH);
#pragma unroll
        for (int k = 0; k < 16; k++) {
            float4 v = Wr2[k];
            wB[2 * k] = pk2(v.x, v.y);
            wB[2 * k + 1] = pk2(v.z, v.w);
        }
    }
    float w0A = 0.f, w0B = 0.f, biasA = 0.f, biasB = 0.f;
    if (L0) {
        w0A = Wih[row0]; w0B = Wih[row1];
        biasA = bih[row0] + bhh[row0];
        biasB = bih[row1] + bhh[row1];
    }
    // activation params: A = m*sig(m*g) - d  (m=2,d=1 for tanh on p1's g-row)
    const float m0 = (p == 1) ? 2.f : 1.f;
    const float d0 = (p == 1) ? 1.f : 0.f;

    // zero h parity 0 (both batches)
    if (j < 32) reinterpret_cast<float4*>(sh_h)[j] = make_float4(0.f, 0.f, 0.f, 0.f);

    // ---- x stream: depth-2 register prefetch, pointer-walk ----
    float  xcs = 0.f, xns = 0.f;                       // L0 scalar
    float2 xc2 = make_float2(0.f, 0.f), xn2 = xc2;     // !L0 packed pair
    const float*  xps = nullptr;    // L0: points at x[t+2]
    const float2* xp2 = nullptr;    // !L0: points at xg pair for t+2
    if (L0) {
        const float* xbase = xin + (size_t)(b0 + b) * SS;
        xcs = xbase[0];
        xns = xbase[1];
        xps = xbase + 2;
    } else {
        const float2* xbase = reinterpret_cast<const float2*>(xin)
                              + ((size_t)(b0 + b) * SS) * 128 + hh * 2 + p;
        xc2 = xbase[0];
        xn2 = xbase[128];
        xp2 = xbase + 256;
    }
    __syncthreads();

    float c = 0.f;

    for (int t = 0; t < SS; ++t) {
        const int pr = t & 1;

        // prefetch t+2 early (pointer-walk, predicated tail)
        float  pfs = 0.f;
        float2 pf2 = make_float2(0.f, 0.f);
        if (L0) { if (t + 2 < SS) pfs = *xps; xps += 1; }
        else    { if (t + 2 < SS) pf2 = *xp2; xp2 += 128; }

        // ax for this step
        float axA, axB;
        if (L0) { axA = fmaf(w0A, xcs, biasA); axB = fmaf(w0B, xcs, biasB); }
        else    { axA = xc2.x; axB = xc2.y; }

        // ---- g = ax + Whh.h_{t-1}: preload bursts (MLP 8) + dual chains ----
        ull a0 = pk2(axA, 0.f);
        ull a1 = pk2(axB, 0.f);
        const ulonglong2* vh = reinterpret_cast<const ulonglong2*>(sh_h[pr][b]);
        {
            ulonglong2 hb[8];
#pragma unroll
            for (int k = 0; k < 8; k++) hb[k] = vh[k];
#pragma unroll
            for (int k = 0; k < 8; k++) {
                a0 = ffma2(wA[2 * k], hb[k].x, a0);
                a0 = ffma2(wA[2 * k + 1], hb[k].y, a0);
                a1 = ffma2(wB[2 * k], hb[k].x, a1);
                a1 = ffma2(wB[2 * k + 1], hb[k].y, a1);
            }
#pragma unroll
            for (int k = 0; k < 8; k++) hb[k] = vh[8 + k];
#pragma unroll
            for (int k = 0; k < 8; k++) {
                a0 = ffma2(wA[16 + 2 * k], hb[k].x, a0);
                a0 = ffma2(wA[17 + 2 * k], hb[k].y, a0);
                a1 = ffma2(wB[16 + 2 * k], hb[k].x, a1);
                a1 = ffma2(wB[17 + 2 * k], hb[k].y, a1);
            }
        }
        float l, h;
        upk2(a0, l, h); float g0 = l + h;
        upk2(a1, l, h); float g1 = l + h;

        // activations: p0 -> (i,f) sigmoids; p1 -> (g tanh, o sigmoid)
        float A0 = m0 * sig_(m0 * g0) - d0;
        float A1 = sig_(g1);

        // pair exchange
        float B0 = __shfl_xor_sync(0xffffffffu, A0, 1);
        float B1 = __shfl_xor_sync(0xffffffffu, A1, 1);
        float iv, fv, gv, ov;
        if (p == 0) { iv = A0; fv = A1; gv = B0; ov = B1; }
        else        { iv = B0; fv = B1; gv = A0; ov = A1; }

        // identical update in both lanes (deterministic)
        c = fv * c + iv * gv;
        float hv2 = ov * tanh_(c);

        if (p == 0) {
            reinterpret_cast<float*>(sh_h[pr ^ 1][b])[hh] = hv2;
        } else {
            hsout[((size_t)(b0 + b) * SS + t) * HH + hh] = hv2;
            if (t == SS - 1) {
                hn[(b0 + b) * HH + hh] = hv2;
                cn[(b0 + b) * HH + hh] = c;
            }
        }
        BATCH_BAR(b);   // only this batch's 4 warps; h_t visible for t+1

        if (L0) { xcs = xns; xns = pfs; }
        else    { xc2 = xn2; xn2 = pf2; }
    }
}

// Final projection: thread-per-output, 16 consecutive LDG.128 per thread.
__global__ __launch_bounds__(256)
void proj_kernel(const float* __restrict__ hs, const float* __restrict__ Wlin,
                 const float* __restrict__ blin, float* __restrict__ y) {
    __shared__ float4 w[16];
    __shared__ float bsh;
    if (threadIdx.x < 16) w[threadIdx.x] = reinterpret_cast<const float4*>(Wlin)[threadIdx.x];
    if (threadIdx.x == 16) bsh = blin[0];
    __syncthreads();
    size_t o = (size_t)blockIdx.x * 256 + threadIdx.x;
    const float4* v = reinterpret_cast<const float4*>(hs + o * HH);
    float acc = 0.f;
#pragma unroll
    for (int k = 0; k < 16; k++) {
        float4 a = v[k];
        float4 b = w[k];
        acc += a.x * b.x + a.y * b.y + a.z * b.z + a.w * b.w;
    }
    y[o] = acc + bsh;
}

extern "C" void kernel_launch(void* const* d_in, const int* in_sizes, int n_in,
                              void* d_out, int out_size) {
    const float* x    = (const float*)d_in[0];
    const float* Wih0 = (const float*)d_in[1];
    const float* Whh0 = (const float*)d_in[2];
    const float* bih0 = (const float*)d_in[3];
    const float* bhh0 = (const float*)d_in[4];
    const float* Wih1 = (const float*)d_in[5];
    const float* Whh1 = (const float*)d_in[6];
    const float* bih1 = (const float*)d_in[7];
    const float* bhh1 = (const float*)d_in[8];
    const float* Wih2 = (const float*)d_in[9];
    const float* Whh2 = (const float*)d_in[10];
    const float* bih2 = (const float*)d_in[11];
    const float* bhh2 = (const float*)d_in[12];
    const float* Wlin = (const float*)d_in[13];
    const float* blin = (const float*)d_in[14];

    float* y  = (float*)d_out;                 // [B,S,1]
    float* hn = y + (size_t)BB * SS;           // [3,B,H]
    float* cn = hn + (size_t)3 * BB * HH;      // [3,B,H]

    float *buf0, *buf1, *xg;
    cudaGetSymbolAddress((void**)&buf0, g_buf0);
    cudaGetSymbolAddress((void**)&buf1, g_buf1);
    cudaGetSymbolAddress((void**)&xg,  g_xg);

    // Layer 0: inline scalar x (DIN=1)
    lstm_scan<true ><<<BB / 2, 256>>>(x, Wih0, Whh0, bih0, bhh0, buf0, hn, cn);
    // Layer 1: precompute interleaved xg, then h-only scan
    xgemm<<<BB, 256>>>(buf0, Wih1, bih1, bhh1, xg);
    lstm_scan<false><<<BB / 2, 256>>>(xg, Wih1, Whh1, bih1, bhh1, buf1,
                                      hn + BB * HH, cn + BB * HH);
    // Layer 2
    xgemm<<<BB, 256>>>(buf1, Wih2, bih2, bhh2, xg);
    lstm_scan<false><<<BB / 2, 256>>>(xg, Wih2, Whh2, bih2, bhh2, buf0,
                                      hn + 2 * BB * HH, cn + 2 * BB * HH);

    proj_kernel<<<(BB * SS) / 256, 256>>>(buf0, Wlin, blin, y);
}